// round 8
// baseline (speedup 1.0000x reference)
#include <cuda_runtime.h>
#include <cuda_bf16.h>
#include <cstdint>

// Problem constants
#define BB      2
#define TT      8192
#define DD      1024
#define HH      8
#define DK      128
#define DV      128
#define CH      64
#define NCH     128
#define BHN     16
#define TTOT    16384
#define NCHUNKS 2048

// -------- scratch (device globals; no allocation allowed) --------
__device__ float g_q [TTOT * DD];
__device__ float g_k [TTOT * DD];
__device__ float g_v [TTOT * DD];
__device__ float g_fq[TTOT * DD];
__device__ float g_fk[TTOT * DD];
__device__ float g_S [(size_t)NCHUNKS * DK * DV];   // S^T[e][d] per chunk
__device__ float g_Z [(size_t)NCHUNKS * DK];
__device__ __nv_bfloat16 g_ahi[(size_t)TTOT * DD];
__device__ __nv_bfloat16 g_alo[(size_t)TTOT * DD];
__device__ __nv_bfloat16 g_wthi[4ull * DD * DD];
__device__ __nv_bfloat16 g_wtlo[4ull * DD * DD];
__device__ __nv_bfloat16 g_fwhi[4 * DK * DK];
__device__ __nv_bfloat16 g_fwlo[4 * DK * DK];

// ============================================================================
// PTX helpers (sm_80+ only)
// ============================================================================
__device__ __forceinline__ uint32_t smem_u32(const void* p) {
    uint32_t a;
    asm("{ .reg .u64 t; cvta.to.shared.u64 t, %1; cvt.u32.u64 %0, t; }" : "=r"(a) : "l"(p));
    return a;
}
#define CP_ASYNC16(dst_u32, src_ptr) \
    asm volatile("cp.async.cg.shared.global [%0], [%1], 16;" :: "r"(dst_u32), "l"(src_ptr) : "memory")
#define CP_COMMIT() asm volatile("cp.async.commit_group;" ::: "memory")
#define CP_WAIT(n)  asm volatile("cp.async.wait_group %0;" :: "n"(n) : "memory")

#define LDSM_X4(r0, r1, r2, r3, addr) \
    asm volatile("ldmatrix.sync.aligned.m8n8.x4.shared.b16 {%0,%1,%2,%3}, [%4];" \
        : "=r"(r0), "=r"(r1), "=r"(r2), "=r"(r3) : "r"(addr))

#define MMA16816(c, a, b) \
    asm volatile("mma.sync.aligned.m16n8k16.row.col.f32.bf16.bf16.f32 " \
        "{%0,%1,%2,%3}, {%4,%5,%6,%7}, {%8,%9}, {%0,%1,%2,%3};" \
        : "+f"((c)[0]), "+f"((c)[1]), "+f"((c)[2]), "+f"((c)[3]) \
        : "r"((a)[0]), "r"((a)[1]), "r"((a)[2]), "r"((a)[3]), "r"((b)[0]), "r"((b)[1]))

__device__ __forceinline__ void split2(float2 v, uint32_t& h, uint32_t& l) {
    __nv_bfloat16 h0 = __float2bfloat16(v.x), h1 = __float2bfloat16(v.y);
    __nv_bfloat16 l0 = __float2bfloat16(v.x - __bfloat162float(h0));
    __nv_bfloat16 l1 = __float2bfloat16(v.y - __bfloat162float(h1));
    __nv_bfloat162 hh = __halves2bfloat162(h0, h1);
    __nv_bfloat162 ll = __halves2bfloat162(l0, l1);
    h = *reinterpret_cast<uint32_t*>(&hh);
    l = *reinterpret_cast<uint32_t*>(&ll);
}
__device__ __forceinline__ void split4(float4 v, uint2& h, uint2& l) {
    uint32_t h0, l0, h1, l1;
    split2(make_float2(v.x, v.y), h0, l0);
    split2(make_float2(v.z, v.w), h1, l1);
    h = make_uint2(h0, h1); l = make_uint2(l0, l1);
}

// ============================================================================
// split / transpose-split kernels
// ============================================================================
__global__ void __launch_bounds__(256) split_kernel(
    const float* __restrict__ in, __nv_bfloat16* __restrict__ hi, __nv_bfloat16* __restrict__ lo)
{
    size_t idx = ((size_t)blockIdx.x * 256 + threadIdx.x) * 8;
    float4 a = *(const float4*)&in[idx];
    float4 b = *(const float4*)&in[idx + 4];
    float v[8] = {a.x, a.y, a.z, a.w, b.x, b.y, b.z, b.w};
    __nv_bfloat16 h[8], l[8];
    #pragma unroll
    for (int t = 0; t < 8; t++) {
        h[t] = __float2bfloat16(v[t]);
        l[t] = __float2bfloat16(v[t] - __bfloat162float(h[t]));
    }
    *(uint4*)&hi[idx] = *(uint4*)h;
    *(uint4*)&lo[idx] = *(uint4*)l;
}

__global__ void transpose_split_kernel(
    const float* __restrict__ W, __nv_bfloat16* __restrict__ hi, __nv_bfloat16* __restrict__ lo)
{
    __shared__ float ts[32][33];
    int tx = threadIdx.x, ty = threadIdx.y;
    int n0 = blockIdx.x * 32, k0 = blockIdx.y * 32;
    for (int i = ty; i < 32; i += 8) ts[i][tx] = W[(size_t)(k0 + i) * DD + n0 + tx];
    __syncthreads();
    for (int i = ty; i < 32; i += 8) {
        float v = ts[tx][i];
        __nv_bfloat16 h = __float2bfloat16(v);
        __nv_bfloat16 l = __float2bfloat16(v - __bfloat162float(h));
        size_t o = (size_t)(n0 + i) * DD + k0 + tx;
        hi[o] = h; lo[o] = l;
    }
}

__global__ void transpose_split128_kernel(
    const float* __restrict__ W, __nv_bfloat16* __restrict__ hi, __nv_bfloat16* __restrict__ lo)
{
    __shared__ float ts[32][33];
    int tx = threadIdx.x, ty = threadIdx.y;
    int n0 = blockIdx.x * 32, k0 = blockIdx.y * 32;
    for (int i = ty; i < 32; i += 8) ts[i][tx] = W[(k0 + i) * DK + n0 + tx];
    __syncthreads();
    for (int i = ty; i < 32; i += 8) {
        float v = ts[tx][i];
        __nv_bfloat16 h = __float2bfloat16(v);
        __nv_bfloat16 l = __float2bfloat16(v - __bfloat162float(h));
        int o = (n0 + i) * DK + k0 + tx;
        hi[o] = h; lo[o] = l;
    }
}

// ============================================================================
// mma.sync bf16 GEMM body (validated)
// ============================================================================
#define MG_STAGE 32768
#define MG_B_OFF 16384
#define MG_SMEM  (3 * MG_STAGE)

__device__ __forceinline__ void mg_load_stage(
    uint32_t stb, int tid, int kt, int rowBase, int colBase,
    const __nv_bfloat16* __restrict__ Ahi, const __nv_bfloat16* __restrict__ Alo,
    const __nv_bfloat16* __restrict__ Bhi, const __nv_bfloat16* __restrict__ Blo)
{
    #pragma unroll
    for (int j = 0; j < 8; j++) {
        int l = tid + j * 256;
        int isB = l >> 10;
        int ll = l & 1023;
        int r = ll >> 3, c = ll & 7;
        const __nv_bfloat16* g;
        int gr;
        if (!isB) { g = (c < 4) ? Ahi : Alo; gr = rowBase + r; }
        else      { g = (c < 4) ? Bhi : Blo; gr = colBase + r; }
        const void* src = g + (size_t)gr * DD + kt + (c & 3) * 8;
        uint32_t off = (uint32_t)(r * 128) + (((uint32_t)c * 16) ^ (((uint32_t)(r & 7)) << 4));
        CP_ASYNC16(stb + isB * MG_B_OFF + off, src);
    }
}

__device__ __forceinline__ void mg_body(
    uint32_t sb, int tid,
    const __nv_bfloat16* __restrict__ Ahi, const __nv_bfloat16* __restrict__ Alo,
    const __nv_bfloat16* __restrict__ Bhi, const __nv_bfloat16* __restrict__ Blo,
    float* __restrict__ C, int rowBase, int colBase)
{
    const int wid  = tid >> 5;
    const int lane = tid & 31;
    const int warp_m = wid >> 2;
    const int warp_n = wid & 3;

    mg_load_stage(sb + 0 * MG_STAGE, tid, 0,  rowBase, colBase, Ahi, Alo, Bhi, Blo);
    CP_COMMIT();
    mg_load_stage(sb + 1 * MG_STAGE, tid, 32, rowBase, colBase, Ahi, Alo, Bhi, Blo);
    CP_COMMIT();

    float acc[4][4][4];
    #pragma unroll
    for (int mi = 0; mi < 4; mi++)
        #pragma unroll
        for (int ni = 0; ni < 4; ni++)
            #pragma unroll
            for (int t = 0; t < 4; t++) acc[mi][ni][t] = 0.f;

    const int aRow  = warp_m * 64 + (lane & 7) + ((lane >> 3) & 1) * 8;
    const uint32_t aKB = ((lane >> 4) & 1) * 16;
    const int bRow  = warp_n * 32 + (lane & 7) + ((lane >> 4) & 1) * 8;
    const uint32_t bKB = ((lane >> 3) & 1) * 16;

    for (int ci = 0; ci < 32; ci++) {
        CP_WAIT(1);
        __syncthreads();
        if (ci + 2 < 32)
            mg_load_stage(sb + ((ci + 2) % 3) * MG_STAGE, tid, (ci + 2) * 32,
                          rowBase, colBase, Ahi, Alo, Bhi, Blo);
        CP_COMMIT();

        uint32_t stb = sb + (ci % 3) * MG_STAGE;
        #pragma unroll
        for (int j = 0; j < 2; j++) {
            uint32_t bh[4][2], bl[4][2];
            #pragma unroll
            for (int ni2 = 0; ni2 < 2; ni2++) {
                int nr = bRow + ni2 * 16;
                uint32_t rbase = stb + MG_B_OFF + nr * 128;
                uint32_t swz = ((uint32_t)(nr & 7)) << 4;
                uint32_t koff = j * 32 + bKB;
                LDSM_X4(bh[ni2 * 2][0], bh[ni2 * 2][1], bh[ni2 * 2 + 1][0], bh[ni2 * 2 + 1][1],
                        rbase + (koff ^ swz));
                LDSM_X4(bl[ni2 * 2][0], bl[ni2 * 2][1], bl[ni2 * 2 + 1][0], bl[ni2 * 2 + 1][1],
                        rbase + ((koff + 64) ^ swz));
            }
            #pragma unroll
            for (int mi = 0; mi < 4; mi++) {
                int ar = aRow + mi * 16;
                uint32_t rbase = stb + ar * 128;
                uint32_t swz = ((uint32_t)(ar & 7)) << 4;
                uint32_t koff = j * 32 + aKB;
                uint32_t ah[4], al[4];
                LDSM_X4(ah[0], ah[1], ah[2], ah[3], rbase + (koff ^ swz));
                LDSM_X4(al[0], al[1], al[2], al[3], rbase + ((koff + 64) ^ swz));
                #pragma unroll
                for (int ni = 0; ni < 4; ni++) {
                    MMA16816(acc[mi][ni], ah, bh[ni]);
                    MMA16816(acc[mi][ni], ah, bl[ni]);
                    MMA16816(acc[mi][ni], al, bh[ni]);
                }
            }
        }
    }

    #pragma unroll
    for (int mi = 0; mi < 4; mi++) {
        int r0 = rowBase + warp_m * 64 + mi * 16 + (lane >> 2);
        #pragma unroll
        for (int ni = 0; ni < 4; ni++) {
            int c0 = colBase + warp_n * 32 + ni * 8 + (lane & 3) * 2;
            *(float2*)&C[(size_t)r0 * DD + c0]       = make_float2(acc[mi][ni][0], acc[mi][ni][1]);
            *(float2*)&C[(size_t)(r0 + 8) * DD + c0] = make_float2(acc[mi][ni][2], acc[mi][ni][3]);
        }
    }
}

__global__ void __launch_bounds__(256, 2) qkv_gemm_kernel(
    const __nv_bfloat16* __restrict__ Ahi, const __nv_bfloat16* __restrict__ Alo,
    const __nv_bfloat16* __restrict__ Bhi0, const __nv_bfloat16* __restrict__ Blo0,
    float* __restrict__ C0, float* __restrict__ C1, float* __restrict__ C2)
{
    extern __shared__ __align__(1024) char smem[];
    uint32_t sb = smem_u32(smem);
    int sel = blockIdx.x >> 3;
    int colBase = (blockIdx.x & 7) * 128;
    const size_t WSZ = (size_t)DD * DD;
    const __nv_bfloat16* Bhi = Bhi0 + (size_t)sel * WSZ;
    const __nv_bfloat16* Blo = Blo0 + (size_t)sel * WSZ;
    float* C = (sel == 0) ? C0 : (sel == 1) ? C1 : C2;
    mg_body(sb, threadIdx.x, Ahi, Alo, Bhi, Blo, C, blockIdx.y * 128, colBase);
}

__global__ void __launch_bounds__(256, 2) mma_gemm_kernel(
    const __nv_bfloat16* __restrict__ Ahi, const __nv_bfloat16* __restrict__ Alo,
    const __nv_bfloat16* __restrict__ Bhi, const __nv_bfloat16* __restrict__ Blo,
    float* __restrict__ C)
{
    extern __shared__ __align__(1024) char smem[];
    uint32_t sb = smem_u32(smem);
    mg_body(sb, threadIdx.x, Ahi, Alo, Bhi, Blo, C, blockIdx.y * 128, blockIdx.x * 128);
}

// ============================================================================
// featmap via mma.sync — merged q/k launch (blockIdx.z selects parameter set)
// ============================================================================
#define FM_AS   132
#define FM_WSB  272
#define FM_W1H  67584
#define FM_W1L  (FM_W1H + 34816)
#define FM_W2H  (FM_W1L + 34816)
#define FM_W2L  (FM_W2H + 34816)
#define FM_SMEM (FM_W2L + 34816)

__global__ void __launch_bounds__(256) featmap_mma_kernel(
    const float* __restrict__ in_q, const float* __restrict__ in_k,
    const __nv_bfloat16* __restrict__ fwhi, const __nv_bfloat16* __restrict__ fwlo,
    const float* __restrict__ bq1, const float* __restrict__ bq2,
    const float* __restrict__ bk1, const float* __restrict__ bk2,
    float* __restrict__ out_q, float* __restrict__ out_k)
{
    extern __shared__ __align__(16) char smem[];
    float* A_s = (float*)smem;
    const int tid = threadIdx.x, wid = tid >> 5, lane = tid & 31;
    const int row0 = blockIdx.x * 128;
    const int h = blockIdx.y;
    const int z = blockIdx.z;
    const float* in = z ? in_k : in_q;
    const float* b1 = z ? bk1 : bq1;
    const float* b2 = z ? bk2 : bq2;
    float* out = z ? out_k : out_q;
    const float scale = z ? 1.0f : 0.08838834764831845f;
    const __nv_bfloat16* w1hi = fwhi + (z * 2 + 0) * DK * DK;
    const __nv_bfloat16* w2hi = fwhi + (z * 2 + 1) * DK * DK;
    const __nv_bfloat16* w1lo = fwlo + (z * 2 + 0) * DK * DK;
    const __nv_bfloat16* w2lo = fwlo + (z * 2 + 1) * DK * DK;
    const size_t base = (size_t)row0 * DD + h * DK;

    #pragma unroll
    for (int i = 0; i < 16; i++) {
        int lin = tid + i * 256;
        int r = lin >> 5, c = (lin & 31) * 4;
        *(float4*)&A_s[r * FM_AS + c] = *(const float4*)&in[base + (size_t)r * DD + c];
    }
    #pragma unroll
    for (int i = 0; i < 8; i++) {
        int lin = tid + i * 256;
        int r = lin >> 4, c8 = lin & 15;
        int gsrc = r * DK + c8 * 8;
        uint32_t doff = (uint32_t)r * FM_WSB + c8 * 16;
        *(uint4*)(smem + FM_W1H + doff) = *(const uint4*)&w1hi[gsrc];
        *(uint4*)(smem + FM_W1L + doff) = *(const uint4*)&w1lo[gsrc];
        *(uint4*)(smem + FM_W2H + doff) = *(const uint4*)&w2hi[gsrc];
        *(uint4*)(smem + FM_W2L + doff) = *(const uint4*)&w2lo[gsrc];
    }
    __syncthreads();

    const int m0 = wid * 16;
    float acc1[16][4], acc2[16][4];
    #pragma unroll
    for (int ni = 0; ni < 16; ni++)
        #pragma unroll
        for (int t = 0; t < 4; t++) { acc1[ni][t] = 0.f; acc2[ni][t] = 0.f; }

    const int ar  = m0 + (lane >> 2);
    const int akc = (lane & 3) * 2;
    const int bn  = lane >> 2;

    for (int kk = 0; kk < 8; kk++) {
        int k0 = kk * 16;
        uint32_t ah[4], al[4];
        split2(*(float2*)&A_s[ar * FM_AS + k0 + akc],           ah[0], al[0]);
        split2(*(float2*)&A_s[(ar + 8) * FM_AS + k0 + akc],     ah[1], al[1]);
        split2(*(float2*)&A_s[ar * FM_AS + k0 + 8 + akc],       ah[2], al[2]);
        split2(*(float2*)&A_s[(ar + 8) * FM_AS + k0 + 8 + akc], ah[3], al[3]);

        uint32_t kb = (uint32_t)(k0 + akc) * 2;
        #pragma unroll
        for (int ni = 0; ni < 16; ni++) {
            uint32_t roff = (uint32_t)(ni * 8 + bn) * FM_WSB + kb;
            uint32_t w1h[2], w1l[2], w2h[2], w2l[2];
            w1h[0] = *(uint32_t*)(smem + FM_W1H + roff);
            w1h[1] = *(uint32_t*)(smem + FM_W1H + roff + 16);
            w1l[0] = *(uint32_t*)(smem + FM_W1L + roff);
            w1l[1] = *(uint32_t*)(smem + FM_W1L + roff + 16);
            w2h[0] = *(uint32_t*)(smem + FM_W2H + roff);
            w2h[1] = *(uint32_t*)(smem + FM_W2H + roff + 16);
            w2l[0] = *(uint32_t*)(smem + FM_W2L + roff);
            w2l[1] = *(uint32_t*)(smem + FM_W2L + roff + 16);
            MMA16816(acc1[ni], ah, w1h);
            MMA16816(acc1[ni], ah, w1l);
            MMA16816(acc1[ni], al, w1h);
            MMA16816(acc2[ni], ah, w2h);
            MMA16816(acc2[ni], ah, w2l);
            MMA16816(acc2[ni], al, w2h);
        }
    }

    const int orow = row0 + m0 + (lane >> 2);
    #pragma unroll
    for (int ni = 0; ni < 16; ni++) {
        int col = ni * 8 + (lane & 3) * 2;
        float2 bb1 = *(const float2*)&b1[col];
        float2 bb2 = *(const float2*)&b2[col];
        float o0 = (acc1[ni][0] + bb1.x) * (acc2[ni][0] + bb2.x) * scale;
        float o1 = (acc1[ni][1] + bb1.y) * (acc2[ni][1] + bb2.y) * scale;
        float o2 = (acc1[ni][2] + bb1.x) * (acc2[ni][2] + bb2.x) * scale;
        float o3 = (acc1[ni][3] + bb1.y) * (acc2[ni][3] + bb2.y) * scale;
        *(float2*)&out[(size_t)orow * DD + h * DK + col]       = make_float2(o0, o1);
        *(float2*)&out[(size_t)(orow + 8) * DD + h * DK + col] = make_float2(o2, o3);
    }
}

// ============================================================================
// chunk_kv via MMA (validated): S_T[e][d] = sum_t v[t][e]*fk[t][d]
// ============================================================================
#define KV_FKT_HI 0
#define KV_FKT_LO 18432
#define KV_VT_HI  36864
#define KV_VT_LO  55296
#define KV_SMEM   73728
#define KV_WS     72

__global__ void __launch_bounds__(256) chunk_kv_mma_kernel()
{
    extern __shared__ __align__(16) char smem[];
    const int tid = threadIdx.x, wid = tid >> 5, lane = tid & 31;
    const int n  = blockIdx.x;
    const int bh = blockIdx.y;
    const int b  = bh >> 3, h = bh & 7;
    const int row0 = b * TT + n * CH;
    const int col0 = h * DK;

    #pragma unroll
    for (int i = 0; i < 8; i++) {
        int lin = tid + i * 256;
        int t = lin >> 5, c4 = (lin & 31) * 4;
        size_t src = (size_t)(row0 + t) * DD + col0 + c4;
        float4 kv = *(const float4*)&g_fk[src];
        float4 vv = *(const float4*)&g_v[src];
        float kk[4] = {kv.x, kv.y, kv.z, kv.w};
        float vw[4] = {vv.x, vv.y, vv.z, vv.w};
        #pragma unroll
        for (int j = 0; j < 4; j++) {
            __nv_bfloat16 kh = __float2bfloat16(kk[j]);
            __nv_bfloat16 kl = __float2bfloat16(kk[j] - __bfloat162float(kh));
            __nv_bfloat16 vh = __float2bfloat16(vw[j]);
            __nv_bfloat16 vl = __float2bfloat16(vw[j] - __bfloat162float(vh));
            int off = (c4 + j) * KV_WS + t;
            *(__nv_bfloat16*)(smem + KV_FKT_HI + off * 2) = kh;
            *(__nv_bfloat16*)(smem + KV_FKT_LO + off * 2) = kl;
            *(__nv_bfloat16*)(smem + KV_VT_HI  + off * 2) = vh;
            *(__nv_bfloat16*)(smem + KV_VT_LO  + off * 2) = vl;
        }
    }
    __syncthreads();

    const int m0 = (wid & 3) * 32;
    const int n0 = (wid >> 2) * 64;
    const int lr = lane >> 2, lk = (lane & 3) * 2;

    float acc[2][8][4];
    #pragma unroll
    for (int mi = 0; mi < 2; mi++)
        #pragma unroll
        for (int ni = 0; ni < 8; ni++)
            #pragma unroll
            for (int t = 0; t < 4; t++) acc[mi][ni][t] = 0.f;

    #pragma unroll
    for (int kk = 0; kk < 4; kk++) {
        int k0 = kk * 16;
        #pragma unroll
        for (int mi = 0; mi < 2; mi++) {
            int mr = m0 + mi * 16 + lr;
            uint32_t ah[4], al[4];
            ah[0] = *(uint32_t*)(smem + KV_VT_HI + (mr * KV_WS + k0 + lk) * 2);
            ah[1] = *(uint32_t*)(smem + KV_VT_HI + ((mr + 8) * KV_WS + k0 + lk) * 2);
            ah[2] = *(uint32_t*)(smem + KV_VT_HI + (mr * KV_WS + k0 + 8 + lk) * 2);
            ah[3] = *(uint32_t*)(smem + KV_VT_HI + ((mr + 8) * KV_WS + k0 + 8 + lk) * 2);
            al[0] = *(uint32_t*)(smem + KV_VT_LO + (mr * KV_WS + k0 + lk) * 2);
            al[1] = *(uint32_t*)(smem + KV_VT_LO + ((mr + 8) * KV_WS + k0 + lk) * 2);
            al[2] = *(uint32_t*)(smem + KV_VT_LO + (mr * KV_WS + k0 + 8 + lk) * 2);
            al[3] = *(uint32_t*)(smem + KV_VT_LO + ((mr + 8) * KV_WS + k0 + 8 + lk) * 2);
            #pragma unroll
            for (int ni = 0; ni < 8; ni++) {
                int nr = n0 + ni * 8 + lr;
                uint32_t bh[2], bl[2];
                bh[0] = *(uint32_t*)(smem + KV_FKT_HI + (nr * KV_WS + k0 + lk) * 2);
                bh[1] = *(uint32_t*)(smem + KV_FKT_HI + (nr * KV_WS + k0 + 8 + lk) * 2);
                bl[0] = *(uint32_t*)(smem + KV_FKT_LO + (nr * KV_WS + k0 + lk) * 2);
                bl[1] = *(uint32_t*)(smem + KV_FKT_LO + (nr * KV_WS + k0 + 8 + lk) * 2);
                MMA16816(acc[mi][ni], ah, bh);
                MMA16816(acc[mi][ni], ah, bl);
                MMA16816(acc[mi][ni], al, bh);
            }
        }
    }

    size_t sb = ((size_t)bh * NCH + n) * (DK * DV);
    #pragma unroll
    for (int mi = 0; mi < 2; mi++) {
        int e0 = m0 + mi * 16 + lr;
        #pragma unroll
        for (int ni = 0; ni < 8; ni++) {
            int d = n0 + ni * 8 + lk;
            *(float2*)&g_S[sb + (size_t)e0 * DV + d]       = make_float2(acc[mi][ni][0], acc[mi][ni][1]);
            *(float2*)&g_S[sb + (size_t)(e0 + 8) * DV + d] = make_float2(acc[mi][ni][2], acc[mi][ni][3]);
        }
    }

    if (tid < 128) {
        float s = 0.f;
        #pragma unroll 8
        for (int t = 0; t < 64; t++) {
            s += __bfloat162float(*(__nv_bfloat16*)(smem + KV_FKT_HI + (tid * KV_WS + t) * 2))
               + __bfloat162float(*(__nv_bfloat16*)(smem + KV_FKT_LO + (tid * KV_WS + t) * 2));
        }
        g_Z[((size_t)bh * NCH + n) * DK + tid] = s;
    }
}

// ============================================================================
// Exclusive prefix scan over chunks — float4 vectorized (4 chains/thread)
// ============================================================================
__global__ void __launch_bounds__(256) scan_kernel()
{
    const int bh  = blockIdx.y;
    const size_t idx4 = ((size_t)blockIdx.x * 256 + threadIdx.x) * 4;

    float4 run = make_float4(0.f, 0.f, 0.f, 0.f);
    size_t base = (size_t)bh * NCH * (DK * DV) + idx4;
    for (int n = 0; n < NCH; n++) {
        size_t a = base + (size_t)n * (DK * DV);
        float4 t = *(float4*)&g_S[a];
        *(float4*)&g_S[a] = run;
        run.x += t.x; run.y += t.y; run.z += t.z; run.w += t.w;
    }
    if (blockIdx.x == 0 && threadIdx.x < DK) {
        float rz = 0.f;
        size_t zb = (size_t)bh * NCH * DK + threadIdx.x;
        for (int n = 0; n < NCH; n++) {
            size_t a = zb + (size_t)n * DK;
            float t = g_Z[a];
            g_Z[a] = rz;
            rz += t;
        }
    }
}

// ============================================================================
// chunk_out, all-MMA main products:
//   A: attn = tril(fq@fk^T)
//   B: o = fq@S_T + attn@v^T  (single fused accumulator, K=128 then K=64)
//   C: den + normalize + RMSNorm; write SPLIT bf16 directly to g_ahi/g_alo.
// ============================================================================
#define CO_FQ_HI 0
#define CO_FQ_LO 17408
#define CO_FK_HI 34816              // o_s (fp32 64x132 = 33792 B) overlays after phase A
#define CO_FK_LO 52224
#define CO_VT_HI 69632              // bf16 128(e) x 72(m)
#define CO_VT_LO 88064
#define CO_S_HI  106496             // bf16 128x136
#define CO_S_LO  141312
#define CO_ATTN  176128             // fp32 64x68
#define CO_Z     193536
#define CO_DEN   194048
#define CO_RED   195072
#define CO_SMEM  196096
#define CO_WS    136
#define CO_VS    132
#define CO_AS2   68
#define CO_VTW   72

__global__ void __launch_bounds__(256) chunk_out_mma_kernel(const float* __restrict__ g_w)
{
    extern __shared__ __align__(16) char smem[];
    const int tid = threadIdx.x, wid = tid >> 5, lane = tid & 31;
    const int n  = blockIdx.x;
    const int bh = blockIdx.y;
    const int b  = bh >> 3, h = bh & 7;
    const int row0 = b * TT + n * CH;
    const int col0 = h * DK;

    float* attn_s = (float*)(smem + CO_ATTN);
    float* Z_s    = (float*)(smem + CO_Z);
    float* den_s  = (float*)(smem + CO_DEN);
    float* red_s  = (float*)(smem + CO_RED);

    // ---- staging ----
    #pragma unroll
    for (int i = 0; i < 8; i++) {
        int lin = tid + i * 256;
        int r = lin >> 5, c4 = (lin & 31) * 4;
        size_t src = (size_t)(row0 + r) * DD + col0 + c4;
        uint2 hh, ll;
        split4(*(const float4*)&g_fq[src], hh, ll);
        *(uint2*)(smem + CO_FQ_HI + (r * CO_WS + c4) * 2) = hh;
        *(uint2*)(smem + CO_FQ_LO + (r * CO_WS + c4) * 2) = ll;
        split4(*(const float4*)&g_fk[src], hh, ll);
        *(uint2*)(smem + CO_FK_HI + (r * CO_WS + c4) * 2) = hh;
        *(uint2*)(smem + CO_FK_LO + (r * CO_WS + c4) * 2) = ll;
        // v transposed split: vT[e][m]
        float4 vv = *(const float4*)&g_v[src];
        float vw[4] = {vv.x, vv.y, vv.z, vv.w};
        #pragma unroll
        for (int j = 0; j < 4; j++) {
            __nv_bfloat16 vh = __float2bfloat16(vw[j]);
            __nv_bfloat16 vl = __float2bfloat16(vw[j] - __bfloat162float(vh));
            int off = (c4 + j) * CO_VTW + r;
            *(__nv_bfloat16*)(smem + CO_VT_HI + off * 2) = vh;
            *(__nv_bfloat16*)(smem + CO_VT_LO + off * 2) = vl;
        }
    }
    size_t sbase = ((size_t)bh * NCH + n) * (DK * DV);
    #pragma unroll
    for (int i = 0; i < 16; i++) {
        int lin = tid + i * 256;
        int r = lin >> 5, c4 = (lin & 31) * 4;
        uint2 hh, ll;
        split4(*(const float4*)&g_S[sbase + (size_t)r * DV + c4], hh, ll);
        *(uint2*)(smem + CO_S_HI + (r * CO_WS + c4) * 2) = hh;
        *(uint2*)(smem + CO_S_LO + (r * CO_WS + c4) * 2) = ll;
    }
    if (tid < 32)
        *(float4*)&Z_s[tid * 4] = *(const float4*)&g_Z[((size_t)bh * NCH + n) * DK + tid * 4];
    __syncthreads();

    const int lr = lane >> 2, lk = (lane & 3) * 2;

    // ---- phase A: attn = fq @ fk^T  (M=64, N=64, K=128) ----
    {
        const int m0 = (wid & 3) * 16;
        const int n0 = (wid >> 2) * 32;
        float acc[4][4];
        #pragma unroll
        for (int ni = 0; ni < 4; ni++)
            #pragma unroll
            for (int t = 0; t < 4; t++) acc[ni][t] = 0.f;

        #pragma unroll
        for (int kk = 0; kk < 8; kk++) {
            int k0 = kk * 16;
            int mr = m0 + lr;
            uint32_t ah[4], al[4];
            ah[0] = *(uint32_t*)(smem + CO_FQ_HI + (mr * CO_WS + k0 + lk) * 2);
            ah[1] = *(uint32_t*)(smem + CO_FQ_HI + ((mr + 8) * CO_WS + k0 + lk) * 2);
            ah[2] = *(uint32_t*)(smem + CO_FQ_HI + (mr * CO_WS + k0 + 8 + lk) * 2);
            ah[3] = *(uint32_t*)(smem + CO_FQ_HI + ((mr + 8) * CO_WS + k0 + 8 + lk) * 2);
            al[0] = *(uint32_t*)(smem + CO_FQ_LO + (mr * CO_WS + k0 + lk) * 2);
            al[1] = *(uint32_t*)(smem + CO_FQ_LO + ((mr + 8) * CO_WS + k0 + lk) * 2);
            al[2] = *(uint32_t*)(smem + CO_FQ_LO + (mr * CO_WS + k0 + 8 + lk) * 2);
            al[3] = *(uint32_t*)(smem + CO_FQ_LO + ((mr + 8) * CO_WS + k0 + 8 + lk) * 2);
            #pragma unroll
            for (int ni = 0; ni < 4; ni++) {
                int nr = n0 + ni * 8 + lr;
                uint32_t bh[2], bl[2];
                bh[0] = *(uint32_t*)(smem + CO_FK_HI + (nr * CO_WS + k0 + lk) * 2);
                bh[1] = *(uint32_t*)(smem + CO_FK_HI + (nr * CO_WS + k0 + 8 + lk) * 2);
                bl[0] = *(uint32_t*)(smem + CO_FK_LO + (nr * CO_WS + k0 + lk) * 2);
                bl[1] = *(uint32_t*)(smem + CO_FK_LO + (nr * CO_WS + k0 + 8 + lk) * 2);
                MMA16816(acc[ni], ah, bh);
                MMA16816(acc[ni], ah, bl);
                MMA16816(acc[ni], al, bh);
            }
        }
        int r0 = m0 + lr, r1 = r0 + 8;
        #pragma unroll
        for (int ni = 0; ni < 4; ni++) {
            int c = n0 + ni * 8 + lk;
            attn_s[r0 * CO_AS2 + c]     = (c     <= r0) ? acc[ni][0] : 0.f;
            attn_s[r0 * CO_AS2 + c + 1] = (c + 1 <= r0) ? acc[ni][1] : 0.f;
            attn_s[r1 * CO_AS2 + c]     = (c     <= r1) ? acc[ni][2] : 0.f;
            attn_s[r1 * CO_AS2 + c + 1] = (c + 1 <= r1) ? acc[ni][3] : 0.f;
        }
    }
    __syncthreads();   // fk reads done; attn published

    // ---- phase B: o = fq @ S_T  +  attn @ v^T  (fused accumulator) ----
    float* o_s = (float*)(smem + CO_FK_HI);   // overlays fk (dead)
    {
        const int m0 = (wid & 3) * 16;
        const int n0 = (wid >> 2) * 64;
        float acc[8][4];
        #pragma unroll
        for (int ni = 0; ni < 8; ni++)
            #pragma unroll
            for (int t = 0; t < 4; t++) acc[ni][t] = 0.f;

        // inter-chunk: K=128 over d
        #pragma unroll
        for (int kk = 0; kk < 8; kk++) {
            int k0 = kk * 16;
            int mr = m0 + lr;
            uint32_t ah[4], al[4];
            ah[0] = *(uint32_t*)(smem + CO_FQ_HI + (mr * CO_WS + k0 + lk) * 2);
            ah[1] = *(uint32_t*)(smem + CO_FQ_HI + ((mr + 8) * CO_WS + k0 + lk) * 2);
            ah[2] = *(uint32_t*)(smem + CO_FQ_HI + (mr * CO_WS + k0 + 8 + lk) * 2);
            ah[3] = *(uint32_t*)(smem + CO_FQ_HI + ((mr + 8) * CO_WS + k0 + 8 + lk) * 2);
            al[0] = *(uint32_t*)(smem + CO_FQ_LO + (mr * CO_WS + k0 + lk) * 2);
            al[1] = *(uint32_t*)(smem + CO_FQ_LO + ((mr + 8) * CO_WS + k0 + lk) * 2);
            al[2] = *(uint32_t*)(smem + CO_FQ_LO + (mr * CO_WS + k0 + 8 + lk) * 2);
            al[3] = *(uint32_t*)(smem + CO_FQ_LO + ((mr + 8) * CO_WS + k0 + 8 + lk) * 2);
            #pragma unroll
            for (int ni = 0; ni < 8; ni++) {
                int nr = n0 + ni * 8 + lr;
                uint32_t bh[2], bl[2];
                bh[0] = *(uint32_t*)(smem + CO_S_HI + (nr * CO_WS + k0 + lk) * 2);
                bh[1] = *(uint32_t*)(smem + CO_S_HI + (nr * CO_WS + k0 + 8 + lk) * 2);
                bl[0] = *(uint32_t*)(smem + CO_S_LO + (nr * CO_WS + k0 + lk) * 2);
                bl[1] = *(uint32_t*)(smem + CO_S_LO + (nr * CO_WS + k0 + 8 + lk) * 2);
                MMA16816(acc[ni], ah, bh);
                MMA16816(acc[ni], ah, bl);
                MMA16816(acc[ni], al, bh);
            }
        }
        // intra-chunk: K=64 over m; A = attn (fp32 smem, split on the fly)
        #pragma unroll
        for (int kk = 0; kk < 4; kk++) {
            int k0 = kk * 16;
            int mr = m0 + lr;
            uint32_t ah[4], al[4];
            split2(*(float2*)&attn_s[mr * CO_AS2 + k0 + lk],           ah[0], al[0]);
            split2(*(float2*)&attn_s[(mr + 8) * CO_AS2 + k0 + lk],     ah[1], al[1]);
            split2(*(float2*)&attn_s[mr * CO_AS2 + k0 + 8 + lk],       ah[2], al[2]);
            split2(*(float2*)&attn_s[(mr + 8) * CO_AS2 + k0 + 8 + lk], ah[3], al[3]);
            #pragma unroll
            for (int ni = 0; ni < 8; ni++) {
                int nr = n0 + ni * 8 + lr;
                uint32_t bh[2], bl[2];
                bh[0] = *(uint32_t*)(smem + CO_VT_HI + (nr * CO_VTW + k0 + lk) * 2);
                bh[1] = *(uint32_t*)(smem + CO_VT_HI + (nr * CO_VTW + k0 + 8 + lk) * 2);
                bl[0] = *(uint32_t*)(smem + CO_VT_LO + (nr * CO_VTW + k0 + lk) * 2);
                bl[1] = *(uint32_t*)(smem + CO_VT_LO + (nr * CO_VTW + k0 + 8 + lk) * 2);
                MMA16816(acc[ni], ah, bh);
                MMA16816(acc[ni], ah, bl);
                MMA16816(acc[ni], al, bh);
            }
        }
        int r0 = m0 + lr;
        #pragma unroll
        for (int ni = 0; ni < 8; ni++) {
            int c = n0 + ni * 8 + lk;
            *(float2*)&o_s[r0 * CO_VS + c]       = make_float2(acc[ni][0], acc[ni][1]);
            *(float2*)&o_s[(r0 + 8) * CO_VS + c] = make_float2(acc[ni][2], acc[ni][3]);
        }
    }
    __syncthreads();

    // ---- phase C: den + normalize + RMSNorm + split writeout ----
    {
        const int r  = tid >> 2;
        const int mq = tid & 3;
        float denp = 0.f;
        #pragma unroll 8
        for (int m = mq * 16; m < mq * 16 + 16; m++)
            denp += attn_s[r * CO_AS2 + m];
        #pragma unroll 8
        for (int d = mq * 32; d < mq * 32 + 32; d++) {
            float qv = __bfloat162float(*(__nv_bfloat16*)(smem + CO_FQ_HI + (r * CO_WS + d) * 2))
                     + __bfloat162float(*(__nv_bfloat16*)(smem + CO_FQ_LO + (r * CO_WS + d) * 2));
            denp += qv * Z_s[d];
        }
        den_s[tid] = denp;
        __syncthreads();
        float den = den_s[r * 4 + 0] + den_s[r * 4 + 1] + den_s[r * 4 + 2] + den_s[r * 4 + 3];
        float dinv = 1.f / (den + 1e-6f);
        float pp = 0.f;
        #pragma unroll 8
        for (int e = mq * 32; e < mq * 32 + 32; e++) {
            float val = o_s[r * CO_VS + e] * dinv;
            pp += val * val;
        }
        red_s[tid] = pp;
        __syncthreads();
        float ms  = (red_s[r * 4 + 0] + red_s[r * 4 + 1] + red_s[r * 4 + 2] + red_s[r * 4 + 3]) * (1.f / 128.f);
        float rms = rsqrtf(ms + 1e-5f);
        size_t obase = (size_t)(row0 + r) * DD + col0;
        #pragma unroll 8
        for (int e = mq * 32; e < mq * 32 + 32; e++) {
            float val = o_s[r * CO_VS + e] * dinv * rms * g_w[e];
            __nv_bfloat16 vh = __float2bfloat16(val);
            __nv_bfloat16 vl = __float2bfloat16(val - __bfloat162float(vh));
            g_ahi[obase + e] = vh;
            g_alo[obase + e] = vl;
        }
    }
}

// ============================================================================
// launch
// ============================================================================
extern "C" void kernel_launch(void* const* d_in, const int* in_sizes, int n_in,
                              void* d_out, int out_size)
{
    const float* x    = (const float*)d_in[0];
    const float* Wq   = (const float*)d_in[1];
    const float* Wk   = (const float*)d_in[2];
    const float* Wv   = (const float*)d_in[3];
    const float* Wo   = (const float*)d_in[4];
    const float* fq1w = (const float*)d_in[5];
    const float* fq1b = (const float*)d_in[6];
    const float* fq2w = (const float*)d_in[7];
    const float* fq2b = (const float*)d_in[8];
    const float* fk1w = (const float*)d_in[9];
    const float* fk1b = (const float*)d_in[10];
    const float* fk2w = (const float*)d_in[11];
    const float* fk2b = (const float*)d_in[12];
    const float* gw   = (const float*)d_in[13];
    float* out = (float*)d_out;

    cudaFuncSetAttribute(qkv_gemm_kernel,      cudaFuncAttributeMaxDynamicSharedMemorySize, MG_SMEM);
    cudaFuncSetAttribute(mma_gemm_kernel,      cudaFuncAttributeMaxDynamicSharedMemorySize, MG_SMEM);
    cudaFuncSetAttribute(featmap_mma_kernel,   cudaFuncAttributeMaxDynamicSharedMemorySize, FM_SMEM);
    cudaFuncSetAttribute(chunk_kv_mma_kernel,  cudaFuncAttributeMaxDynamicSharedMemorySize, KV_SMEM);
    cudaFuncSetAttribute(chunk_out_mma_kernel, cudaFuncAttributeMaxDynamicSharedMemorySize, CO_SMEM);

    float *q_p, *k_p, *v_p, *fq_p, *fk_p;
    __nv_bfloat16 *ahi_p, *alo_p, *wthi_p, *wtlo_p, *fwhi_p, *fwlo_p;
    cudaGetSymbolAddress((void**)&q_p,  g_q);
    cudaGetSymbolAddress((void**)&k_p,  g_k);
    cudaGetSymbolAddress((void**)&v_p,  g_v);
    cudaGetSymbolAddress((void**)&fq_p, g_fq);
    cudaGetSymbolAddress((void**)&fk_p, g_fk);
    cudaGetSymbolAddress((void**)&ahi_p, g_ahi);
    cudaGetSymbolAddress((void**)&alo_p, g_alo);
    cudaGetSymbolAddress((void**)&wthi_p, g_wthi);
    cudaGetSymbolAddress((void**)&wtlo_p, g_wtlo);
    cudaGetSymbolAddress((void**)&fwhi_p, g_fwhi);
    cudaGetSymbolAddress((void**)&fwlo_p, g_fwlo);

    const size_t WSZ = (size_t)DD * DD;
    const int FWSZ = DK * DK;
    dim3 tblk(32, 8), tgrd(32, 32), tgrd128(4, 4);
    transpose_split_kernel<<<tgrd, tblk>>>(Wq, wthi_p + 0 * WSZ, wtlo_p + 0 * WSZ);
    transpose_split_kernel<<<tgrd, tblk>>>(Wk, wthi_p + 1 * WSZ, wtlo_p + 1 * WSZ);
    transpose_split_kernel<<<tgrd, tblk>>>(Wv, wthi_p + 2 * WSZ, wtlo_p + 2 * WSZ);
    transpose_split_kernel<<<tgrd, tblk>>>(Wo, wthi_p + 3 * WSZ, wtlo_p + 3 * WSZ);
    transpose_split128_kernel<<<tgrd128, tblk>>>(fq1w, fwhi_p + 0 * FWSZ, fwlo_p + 0 * FWSZ);
    transpose_split128_kernel<<<tgrd128, tblk>>>(fq2w, fwhi_p + 1 * FWSZ, fwlo_p + 1 * FWSZ);
    transpose_split128_kernel<<<tgrd128, tblk>>>(fk1w, fwhi_p + 2 * FWSZ, fwlo_p + 2 * FWSZ);
    transpose_split128_kernel<<<tgrd128, tblk>>>(fk2w, fwhi_p + 3 * FWSZ, fwlo_p + 3 * FWSZ);

    split_kernel<<<8192, 256>>>(x, ahi_p, alo_p);

    qkv_gemm_kernel<<<dim3(24, TTOT / 128), 256, MG_SMEM>>>(
        ahi_p, alo_p, wthi_p, wtlo_p, q_p, k_p, v_p);

    featmap_mma_kernel<<<dim3(TTOT / 128, HH, 2), 256, FM_SMEM>>>(
        q_p, k_p, fwhi_p, fwlo_p, fq1b, fq2b, fk1b, fk2b, fq_p, fk_p);

    chunk_kv_mma_kernel<<<dim3(NCH, BHN), 256, KV_SMEM>>>();
    scan_kernel<<<dim3(16, BHN), 256>>>();
    chunk_out_mma_kernel<<<dim3(NCH, BHN), 256, CO_SMEM>>>(gw);

    // chunk_out wrote split o into g_ahi/g_alo directly
    mma_gemm_kernel<<<dim3(DD / 128, TTOT / 128), 256, MG_SMEM>>>(
        ahi_p, alo_p, wthi_p + 3 * WSZ, wtlo_p + 3 * WSZ, out);
}

// round 9
// speedup vs baseline: 1.0577x; 1.0577x over previous
#include <cuda_runtime.h>
#include <cuda_bf16.h>
#include <cstdint>

// Problem constants
#define BB      2
#define TT      8192
#define DD      1024
#define HH      8
#define DK      128
#define DV      128
#define CH      64
#define NCH     128
#define BHN     16
#define TTOT    16384
#define NCHUNKS 2048

// -------- scratch (device globals; no allocation allowed) --------
__device__ float g_q [TTOT * DD];
__device__ float g_k [TTOT * DD];
__device__ float g_v [TTOT * DD];
__device__ float g_fq[TTOT * DD];
__device__ float g_fk[TTOT * DD];
__device__ float g_o [TTOT * DD];
__device__ float g_S [(size_t)NCHUNKS * DK * DV];   // S^T[e][d] per chunk
__device__ float g_Z [(size_t)NCHUNKS * DK];
__device__ __nv_bfloat16 g_ahi[(size_t)TTOT * DD];
__device__ __nv_bfloat16 g_alo[(size_t)TTOT * DD];
__device__ __nv_bfloat16 g_wthi[4ull * DD * DD];
__device__ __nv_bfloat16 g_wtlo[4ull * DD * DD];
__device__ __nv_bfloat16 g_fwhi[4 * DK * DK];
__device__ __nv_bfloat16 g_fwlo[4 * DK * DK];

// ============================================================================
// PTX helpers (sm_80+ only)
// ============================================================================
__device__ __forceinline__ uint32_t smem_u32(const void* p) {
    uint32_t a;
    asm("{ .reg .u64 t; cvta.to.shared.u64 t, %1; cvt.u32.u64 %0, t; }" : "=r"(a) : "l"(p));
    return a;
}
#define CP_ASYNC16(dst_u32, src_ptr) \
    asm volatile("cp.async.cg.shared.global [%0], [%1], 16;" :: "r"(dst_u32), "l"(src_ptr) : "memory")
#define CP_COMMIT() asm volatile("cp.async.commit_group;" ::: "memory")
#define CP_WAIT(n)  asm volatile("cp.async.wait_group %0;" :: "n"(n) : "memory")

#define LDSM_X4(r0, r1, r2, r3, addr) \
    asm volatile("ldmatrix.sync.aligned.m8n8.x4.shared.b16 {%0,%1,%2,%3}, [%4];" \
        : "=r"(r0), "=r"(r1), "=r"(r2), "=r"(r3) : "r"(addr))

#define MMA16816(c, a, b) \
    asm volatile("mma.sync.aligned.m16n8k16.row.col.f32.bf16.bf16.f32 " \
        "{%0,%1,%2,%3}, {%4,%5,%6,%7}, {%8,%9}, {%0,%1,%2,%3};" \
        : "+f"((c)[0]), "+f"((c)[1]), "+f"((c)[2]), "+f"((c)[3]) \
        : "r"((a)[0]), "r"((a)[1]), "r"((a)[2]), "r"((a)[3]), "r"((b)[0]), "r"((b)[1]))

__device__ __forceinline__ void split2(float2 v, uint32_t& h, uint32_t& l) {
    __nv_bfloat16 h0 = __float2bfloat16(v.x), h1 = __float2bfloat16(v.y);
    __nv_bfloat16 l0 = __float2bfloat16(v.x - __bfloat162float(h0));
    __nv_bfloat16 l1 = __float2bfloat16(v.y - __bfloat162float(h1));
    __nv_bfloat162 hh = __halves2bfloat162(h0, h1);
    __nv_bfloat162 ll = __halves2bfloat162(l0, l1);
    h = *reinterpret_cast<uint32_t*>(&hh);
    l = *reinterpret_cast<uint32_t*>(&ll);
}
__device__ __forceinline__ void split4(float4 v, uint2& h, uint2& l) {
    uint32_t h0, l0, h1, l1;
    split2(make_float2(v.x, v.y), h0, l0);
    split2(make_float2(v.z, v.w), h1, l1);
    h = make_uint2(h0, h1); l = make_uint2(l0, l1);
}

// ============================================================================
// split / transpose-split kernels
// ============================================================================
__global__ void __launch_bounds__(256) split_kernel(
    const float* __restrict__ in, __nv_bfloat16* __restrict__ hi, __nv_bfloat16* __restrict__ lo)
{
    size_t idx = ((size_t)blockIdx.x * 256 + threadIdx.x) * 8;
    float4 a = *(const float4*)&in[idx];
    float4 b = *(const float4*)&in[idx + 4];
    float v[8] = {a.x, a.y, a.z, a.w, b.x, b.y, b.z, b.w};
    __nv_bfloat16 h[8], l[8];
    #pragma unroll
    for (int t = 0; t < 8; t++) {
        h[t] = __float2bfloat16(v[t]);
        l[t] = __float2bfloat16(v[t] - __bfloat162float(h[t]));
    }
    *(uint4*)&hi[idx] = *(uint4*)h;
    *(uint4*)&lo[idx] = *(uint4*)l;
}

__global__ void transpose_split_kernel(
    const float* __restrict__ W, __nv_bfloat16* __restrict__ hi, __nv_bfloat16* __restrict__ lo)
{
    __shared__ float ts[32][33];
    int tx = threadIdx.x, ty = threadIdx.y;
    int n0 = blockIdx.x * 32, k0 = blockIdx.y * 32;
    for (int i = ty; i < 32; i += 8) ts[i][tx] = W[(size_t)(k0 + i) * DD + n0 + tx];
    __syncthreads();
    for (int i = ty; i < 32; i += 8) {
        float v = ts[tx][i];
        __nv_bfloat16 h = __float2bfloat16(v);
        __nv_bfloat16 l = __float2bfloat16(v - __bfloat162float(h));
        size_t o = (size_t)(n0 + i) * DD + k0 + tx;
        hi[o] = h; lo[o] = l;
    }
}

__global__ void transpose_split128_kernel(
    const float* __restrict__ W, __nv_bfloat16* __restrict__ hi, __nv_bfloat16* __restrict__ lo)
{
    __shared__ float ts[32][33];
    int tx = threadIdx.x, ty = threadIdx.y;
    int n0 = blockIdx.x * 32, k0 = blockIdx.y * 32;
    for (int i = ty; i < 32; i += 8) ts[i][tx] = W[(k0 + i) * DK + n0 + tx];
    __syncthreads();
    for (int i = ty; i < 32; i += 8) {
        float v = ts[tx][i];
        __nv_bfloat16 h = __float2bfloat16(v);
        __nv_bfloat16 l = __float2bfloat16(v - __bfloat162float(h));
        int o = (n0 + i) * DK + k0 + tx;
        hi[o] = h; lo[o] = l;
    }
}

// ============================================================================
// mma.sync bf16 GEMM body (validated)
// ============================================================================
#define MG_STAGE 32768
#define MG_B_OFF 16384
#define MG_SMEM  (3 * MG_STAGE)

__device__ __forceinline__ void mg_load_stage(
    uint32_t stb, int tid, int kt, int rowBase, int colBase,
    const __nv_bfloat16* __restrict__ Ahi, const __nv_bfloat16* __restrict__ Alo,
    const __nv_bfloat16* __restrict__ Bhi, const __nv_bfloat16* __restrict__ Blo)
{
    #pragma unroll
    for (int j = 0; j < 8; j++) {
        int l = tid + j * 256;
        int isB = l >> 10;
        int ll = l & 1023;
        int r = ll >> 3, c = ll & 7;
        const __nv_bfloat16* g;
        int gr;
        if (!isB) { g = (c < 4) ? Ahi : Alo; gr = rowBase + r; }
        else      { g = (c < 4) ? Bhi : Blo; gr = colBase + r; }
        const void* src = g + (size_t)gr * DD + kt + (c & 3) * 8;
        uint32_t off = (uint32_t)(r * 128) + (((uint32_t)c * 16) ^ (((uint32_t)(r & 7)) << 4));
        CP_ASYNC16(stb + isB * MG_B_OFF + off, src);
    }
}

__device__ __forceinline__ void mg_body(
    uint32_t sb, int tid,
    const __nv_bfloat16* __restrict__ Ahi, const __nv_bfloat16* __restrict__ Alo,
    const __nv_bfloat16* __restrict__ Bhi, const __nv_bfloat16* __restrict__ Blo,
    float* __restrict__ C, int rowBase, int colBase)
{
    const int wid  = tid >> 5;
    const int lane = tid & 31;
    const int warp_m = wid >> 2;
    const int warp_n = wid & 3;

    mg_load_stage(sb + 0 * MG_STAGE, tid, 0,  rowBase, colBase, Ahi, Alo, Bhi, Blo);
    CP_COMMIT();
    mg_load_stage(sb + 1 * MG_STAGE, tid, 32, rowBase, colBase, Ahi, Alo, Bhi, Blo);
    CP_COMMIT();

    float acc[4][4][4];
    #pragma unroll
    for (int mi = 0; mi < 4; mi++)
        #pragma unroll
        for (int ni = 0; ni < 4; ni++)
            #pragma unroll
            for (int t = 0; t < 4; t++) acc[mi][ni][t] = 0.f;

    const int aRow  = warp_m * 64 + (lane & 7) + ((lane >> 3) & 1) * 8;
    const uint32_t aKB = ((lane >> 4) & 1) * 16;
    const int bRow  = warp_n * 32 + (lane & 7) + ((lane >> 4) & 1) * 8;
    const uint32_t bKB = ((lane >> 3) & 1) * 16;

    for (int ci = 0; ci < 32; ci++) {
        CP_WAIT(1);
        __syncthreads();
        if (ci + 2 < 32)
            mg_load_stage(sb + ((ci + 2) % 3) * MG_STAGE, tid, (ci + 2) * 32,
                          rowBase, colBase, Ahi, Alo, Bhi, Blo);
        CP_COMMIT();

        uint32_t stb = sb + (ci % 3) * MG_STAGE;
        #pragma unroll
        for (int j = 0; j < 2; j++) {
            uint32_t bh[4][2], bl[4][2];
            #pragma unroll
            for (int ni2 = 0; ni2 < 2; ni2++) {
                int nr = bRow + ni2 * 16;
                uint32_t rbase = stb + MG_B_OFF + nr * 128;
                uint32_t swz = ((uint32_t)(nr & 7)) << 4;
                uint32_t koff = j * 32 + bKB;
                LDSM_X4(bh[ni2 * 2][0], bh[ni2 * 2][1], bh[ni2 * 2 + 1][0], bh[ni2 * 2 + 1][1],
                        rbase + (koff ^ swz));
                LDSM_X4(bl[ni2 * 2][0], bl[ni2 * 2][1], bl[ni2 * 2 + 1][0], bl[ni2 * 2 + 1][1],
                        rbase + ((koff + 64) ^ swz));
            }
            #pragma unroll
            for (int mi = 0; mi < 4; mi++) {
                int ar = aRow + mi * 16;
                uint32_t rbase = stb + ar * 128;
                uint32_t swz = ((uint32_t)(ar & 7)) << 4;
                uint32_t koff = j * 32 + aKB;
                uint32_t ah[4], al[4];
                LDSM_X4(ah[0], ah[1], ah[2], ah[3], rbase + (koff ^ swz));
                LDSM_X4(al[0], al[1], al[2], al[3], rbase + ((koff + 64) ^ swz));
                #pragma unroll
                for (int ni = 0; ni < 4; ni++) {
                    MMA16816(acc[mi][ni], ah, bh[ni]);
                    MMA16816(acc[mi][ni], ah, bl[ni]);
                    MMA16816(acc[mi][ni], al, bh[ni]);
                }
            }
        }
    }

    #pragma unroll
    for (int mi = 0; mi < 4; mi++) {
        int r0 = rowBase + warp_m * 64 + mi * 16 + (lane >> 2);
        #pragma unroll
        for (int ni = 0; ni < 4; ni++) {
            int c0 = colBase + warp_n * 32 + ni * 8 + (lane & 3) * 2;
            *(float2*)&C[(size_t)r0 * DD + c0]       = make_float2(acc[mi][ni][0], acc[mi][ni][1]);
            *(float2*)&C[(size_t)(r0 + 8) * DD + c0] = make_float2(acc[mi][ni][2], acc[mi][ni][3]);
        }
    }
}

__global__ void __launch_bounds__(256, 2) qkv_gemm_kernel(
    const __nv_bfloat16* __restrict__ Ahi, const __nv_bfloat16* __restrict__ Alo,
    const __nv_bfloat16* __restrict__ Bhi0, const __nv_bfloat16* __restrict__ Blo0,
    float* __restrict__ C0, float* __restrict__ C1, float* __restrict__ C2)
{
    extern __shared__ __align__(1024) char smem[];
    uint32_t sb = smem_u32(smem);
    int sel = blockIdx.x >> 3;
    int colBase = (blockIdx.x & 7) * 128;
    const size_t WSZ = (size_t)DD * DD;
    const __nv_bfloat16* Bhi = Bhi0 + (size_t)sel * WSZ;
    const __nv_bfloat16* Blo = Blo0 + (size_t)sel * WSZ;
    float* C = (sel == 0) ? C0 : (sel == 1) ? C1 : C2;
    mg_body(sb, threadIdx.x, Ahi, Alo, Bhi, Blo, C, blockIdx.y * 128, colBase);
}

__global__ void __launch_bounds__(256, 2) mma_gemm_kernel(
    const __nv_bfloat16* __restrict__ Ahi, const __nv_bfloat16* __restrict__ Alo,
    const __nv_bfloat16* __restrict__ Bhi, const __nv_bfloat16* __restrict__ Blo,
    float* __restrict__ C)
{
    extern __shared__ __align__(1024) char smem[];
    uint32_t sb = smem_u32(smem);
    mg_body(sb, threadIdx.x, Ahi, Alo, Bhi, Blo, C, blockIdx.y * 128, blockIdx.x * 128);
}

// ============================================================================
// featmap via mma.sync — merged q/k launch (blockIdx.z selects parameter set)
// ============================================================================
#define FM_AS   132
#define FM_WSB  272
#define FM_W1H  67584
#define FM_W1L  (FM_W1H + 34816)
#define FM_W2H  (FM_W1L + 34816)
#define FM_W2L  (FM_W2H + 34816)
#define FM_SMEM (FM_W2L + 34816)

__global__ void __launch_bounds__(256) featmap_mma_kernel(
    const float* __restrict__ in_q, const float* __restrict__ in_k,
    const __nv_bfloat16* __restrict__ fwhi, const __nv_bfloat16* __restrict__ fwlo,
    const float* __restrict__ bq1, const float* __restrict__ bq2,
    const float* __restrict__ bk1, const float* __restrict__ bk2,
    float* __restrict__ out_q, float* __restrict__ out_k)
{
    extern __shared__ __align__(16) char smem[];
    float* A_s = (float*)smem;
    const int tid = threadIdx.x, wid = tid >> 5, lane = tid & 31;
    const int row0 = blockIdx.x * 128;
    const int h = blockIdx.y;
    const int z = blockIdx.z;
    const float* in = z ? in_k : in_q;
    const float* b1 = z ? bk1 : bq1;
    const float* b2 = z ? bk2 : bq2;
    float* out = z ? out_k : out_q;
    const float scale = z ? 1.0f : 0.08838834764831845f;
    const __nv_bfloat16* w1hi = fwhi + (z * 2 + 0) * DK * DK;
    const __nv_bfloat16* w2hi = fwhi + (z * 2 + 1) * DK * DK;
    const __nv_bfloat16* w1lo = fwlo + (z * 2 + 0) * DK * DK;
    const __nv_bfloat16* w2lo = fwlo + (z * 2 + 1) * DK * DK;
    const size_t base = (size_t)row0 * DD + h * DK;

    #pragma unroll
    for (int i = 0; i < 16; i++) {
        int lin = tid + i * 256;
        int r = lin >> 5, c = (lin & 31) * 4;
        *(float4*)&A_s[r * FM_AS + c] = *(const float4*)&in[base + (size_t)r * DD + c];
    }
    #pragma unroll
    for (int i = 0; i < 8; i++) {
        int lin = tid + i * 256;
        int r = lin >> 4, c8 = lin & 15;
        int gsrc = r * DK + c8 * 8;
        uint32_t doff = (uint32_t)r * FM_WSB + c8 * 16;
        *(uint4*)(smem + FM_W1H + doff) = *(const uint4*)&w1hi[gsrc];
        *(uint4*)(smem + FM_W1L + doff) = *(const uint4*)&w1lo[gsrc];
        *(uint4*)(smem + FM_W2H + doff) = *(const uint4*)&w2hi[gsrc];
        *(uint4*)(smem + FM_W2L + doff) = *(const uint4*)&w2lo[gsrc];
    }
    __syncthreads();

    const int m0 = wid * 16;
    float acc1[16][4], acc2[16][4];
    #pragma unroll
    for (int ni = 0; ni < 16; ni++)
        #pragma unroll
        for (int t = 0; t < 4; t++) { acc1[ni][t] = 0.f; acc2[ni][t] = 0.f; }

    const int ar  = m0 + (lane >> 2);
    const int akc = (lane & 3) * 2;
    const int bn  = lane >> 2;

    for (int kk = 0; kk < 8; kk++) {
        int k0 = kk * 16;
        uint32_t ah[4], al[4];
        split2(*(float2*)&A_s[ar * FM_AS + k0 + akc],           ah[0], al[0]);
        split2(*(float2*)&A_s[(ar + 8) * FM_AS + k0 + akc],     ah[1], al[1]);
        split2(*(float2*)&A_s[ar * FM_AS + k0 + 8 + akc],       ah[2], al[2]);
        split2(*(float2*)&A_s[(ar + 8) * FM_AS + k0 + 8 + akc], ah[3], al[3]);

        uint32_t kb = (uint32_t)(k0 + akc) * 2;
        #pragma unroll
        for (int ni = 0; ni < 16; ni++) {
            uint32_t roff = (uint32_t)(ni * 8 + bn) * FM_WSB + kb;
            uint32_t w1h[2], w1l[2], w2h[2], w2l[2];
            w1h[0] = *(uint32_t*)(smem + FM_W1H + roff);
            w1h[1] = *(uint32_t*)(smem + FM_W1H + roff + 16);
            w1l[0] = *(uint32_t*)(smem + FM_W1L + roff);
            w1l[1] = *(uint32_t*)(smem + FM_W1L + roff + 16);
            w2h[0] = *(uint32_t*)(smem + FM_W2H + roff);
            w2h[1] = *(uint32_t*)(smem + FM_W2H + roff + 16);
            w2l[0] = *(uint32_t*)(smem + FM_W2L + roff);
            w2l[1] = *(uint32_t*)(smem + FM_W2L + roff + 16);
            MMA16816(acc1[ni], ah, w1h);
            MMA16816(acc1[ni], ah, w1l);
            MMA16816(acc1[ni], al, w1h);
            MMA16816(acc2[ni], ah, w2h);
            MMA16816(acc2[ni], ah, w2l);
            MMA16816(acc2[ni], al, w2h);
        }
    }

    const int orow = row0 + m0 + (lane >> 2);
    #pragma unroll
    for (int ni = 0; ni < 16; ni++) {
        int col = ni * 8 + (lane & 3) * 2;
        float2 bb1 = *(const float2*)&b1[col];
        float2 bb2 = *(const float2*)&b2[col];
        float o0 = (acc1[ni][0] + bb1.x) * (acc2[ni][0] + bb2.x) * scale;
        float o1 = (acc1[ni][1] + bb1.y) * (acc2[ni][1] + bb2.y) * scale;
        float o2 = (acc1[ni][2] + bb1.x) * (acc2[ni][2] + bb2.x) * scale;
        float o3 = (acc1[ni][3] + bb1.y) * (acc2[ni][3] + bb2.y) * scale;
        *(float2*)&out[(size_t)orow * DD + h * DK + col]       = make_float2(o0, o1);
        *(float2*)&out[(size_t)(orow + 8) * DD + h * DK + col] = make_float2(o2, o3);
    }
}

// ============================================================================
// chunk_kv via MMA (validated): S_T[e][d] = sum_t v[t][e]*fk[t][d]
// ============================================================================
#define KV_FKT_HI 0
#define KV_FKT_LO 18432
#define KV_VT_HI  36864
#define KV_VT_LO  55296
#define KV_SMEM   73728
#define KV_WS     72

__global__ void __launch_bounds__(256) chunk_kv_mma_kernel()
{
    extern __shared__ __align__(16) char smem[];
    const int tid = threadIdx.x, wid = tid >> 5, lane = tid & 31;
    const int n  = blockIdx.x;
    const int bh = blockIdx.y;
    const int b  = bh >> 3, h = bh & 7;
    const int row0 = b * TT + n * CH;
    const int col0 = h * DK;

    #pragma unroll
    for (int i = 0; i < 8; i++) {
        int lin = tid + i * 256;
        int t = lin >> 5, c4 = (lin & 31) * 4;
        size_t src = (size_t)(row0 + t) * DD + col0 + c4;
        float4 kv = *(const float4*)&g_fk[src];
        float4 vv = *(const float4*)&g_v[src];
        float kk[4] = {kv.x, kv.y, kv.z, kv.w};
        float vw[4] = {vv.x, vv.y, vv.z, vv.w};
        #pragma unroll
        for (int j = 0; j < 4; j++) {
            __nv_bfloat16 kh = __float2bfloat16(kk[j]);
            __nv_bfloat16 kl = __float2bfloat16(kk[j] - __bfloat162float(kh));
            __nv_bfloat16 vh = __float2bfloat16(vw[j]);
            __nv_bfloat16 vl = __float2bfloat16(vw[j] - __bfloat162float(vh));
            int off = (c4 + j) * KV_WS + t;
            *(__nv_bfloat16*)(smem + KV_FKT_HI + off * 2) = kh;
            *(__nv_bfloat16*)(smem + KV_FKT_LO + off * 2) = kl;
            *(__nv_bfloat16*)(smem + KV_VT_HI  + off * 2) = vh;
            *(__nv_bfloat16*)(smem + KV_VT_LO  + off * 2) = vl;
        }
    }
    __syncthreads();

    const int m0 = (wid & 3) * 32;
    const int n0 = (wid >> 2) * 64;
    const int lr = lane >> 2, lk = (lane & 3) * 2;

    float acc[2][8][4];
    #pragma unroll
    for (int mi = 0; mi < 2; mi++)
        #pragma unroll
        for (int ni = 0; ni < 8; ni++)
            #pragma unroll
            for (int t = 0; t < 4; t++) acc[mi][ni][t] = 0.f;

    #pragma unroll
    for (int kk = 0; kk < 4; kk++) {
        int k0 = kk * 16;
        #pragma unroll
        for (int mi = 0; mi < 2; mi++) {
            int mr = m0 + mi * 16 + lr;
            uint32_t ah[4], al[4];
            ah[0] = *(uint32_t*)(smem + KV_VT_HI + (mr * KV_WS + k0 + lk) * 2);
            ah[1] = *(uint32_t*)(smem + KV_VT_HI + ((mr + 8) * KV_WS + k0 + lk) * 2);
            ah[2] = *(uint32_t*)(smem + KV_VT_HI + (mr * KV_WS + k0 + 8 + lk) * 2);
            ah[3] = *(uint32_t*)(smem + KV_VT_HI + ((mr + 8) * KV_WS + k0 + 8 + lk) * 2);
            al[0] = *(uint32_t*)(smem + KV_VT_LO + (mr * KV_WS + k0 + lk) * 2);
            al[1] = *(uint32_t*)(smem + KV_VT_LO + ((mr + 8) * KV_WS + k0 + lk) * 2);
            al[2] = *(uint32_t*)(smem + KV_VT_LO + (mr * KV_WS + k0 + 8 + lk) * 2);
            al[3] = *(uint32_t*)(smem + KV_VT_LO + ((mr + 8) * KV_WS + k0 + 8 + lk) * 2);
            #pragma unroll
            for (int ni = 0; ni < 8; ni++) {
                int nr = n0 + ni * 8 + lr;
                uint32_t bh[2], bl[2];
                bh[0] = *(uint32_t*)(smem + KV_FKT_HI + (nr * KV_WS + k0 + lk) * 2);
                bh[1] = *(uint32_t*)(smem + KV_FKT_HI + (nr * KV_WS + k0 + 8 + lk) * 2);
                bl[0] = *(uint32_t*)(smem + KV_FKT_LO + (nr * KV_WS + k0 + lk) * 2);
                bl[1] = *(uint32_t*)(smem + KV_FKT_LO + (nr * KV_WS + k0 + 8 + lk) * 2);
                MMA16816(acc[mi][ni], ah, bh);
                MMA16816(acc[mi][ni], ah, bl);
                MMA16816(acc[mi][ni], al, bh);
            }
        }
    }

    size_t sb = ((size_t)bh * NCH + n) * (DK * DV);
    #pragma unroll
    for (int mi = 0; mi < 2; mi++) {
        int e0 = m0 + mi * 16 + lr;
        #pragma unroll
        for (int ni = 0; ni < 8; ni++) {
            int d = n0 + ni * 8 + lk;
            *(float2*)&g_S[sb + (size_t)e0 * DV + d]       = make_float2(acc[mi][ni][0], acc[mi][ni][1]);
            *(float2*)&g_S[sb + (size_t)(e0 + 8) * DV + d] = make_float2(acc[mi][ni][2], acc[mi][ni][3]);
        }
    }

    if (tid < 128) {
        float s = 0.f;
        #pragma unroll 8
        for (int t = 0; t < 64; t++) {
            s += __bfloat162float(*(__nv_bfloat16*)(smem + KV_FKT_HI + (tid * KV_WS + t) * 2))
               + __bfloat162float(*(__nv_bfloat16*)(smem + KV_FKT_LO + (tid * KV_WS + t) * 2));
        }
        g_Z[((size_t)bh * NCH + n) * DK + tid] = s;
    }
}

// ============================================================================
// Exclusive prefix scan over chunks — float4 vectorized (kept from R8)
// ============================================================================
__global__ void __launch_bounds__(256) scan_kernel()
{
    const int bh  = blockIdx.y;
    const size_t idx4 = ((size_t)blockIdx.x * 256 + threadIdx.x) * 4;

    float4 run = make_float4(0.f, 0.f, 0.f, 0.f);
    size_t base = (size_t)bh * NCH * (DK * DV) + idx4;
    for (int n = 0; n < NCH; n++) {
        size_t a = base + (size_t)n * (DK * DV);
        float4 t = *(float4*)&g_S[a];
        *(float4*)&g_S[a] = run;
        run.x += t.x; run.y += t.y; run.z += t.z; run.w += t.w;
    }
    if (blockIdx.x == 0 && threadIdx.x < DK) {
        float rz = 0.f;
        size_t zb = (size_t)bh * NCH * DK + threadIdx.x;
        for (int n = 0; n < NCH; n++) {
            size_t a = zb + (size_t)n * DK;
            float t = g_Z[a];
            g_Z[a] = rz;
            rz += t;
        }
    }
}

// ============================================================================
// chunk_out — REVERTED to R7 structure (MMA phases A/B, FFMA attn@v, fp32 g_o)
// with float4-vectorized epilogue stores.
// ============================================================================
#define CO_FQ_HI 0
#define CO_FQ_LO 17408
#define CO_FK_HI 34816              // o_s (fp32 64x132) overlays after phase A
#define CO_FK_LO 52224
#define CO_V     69632              // fp32 64x132
#define CO_S_HI  103424             // bf16 128x136
#define CO_S_LO  138240
#define CO_ATTN  173056             // fp32 64x68
#define CO_Z     190464
#define CO_DEN   190976
#define CO_RED   192000
#define CO_SMEM  193024
#define CO_WS    136
#define CO_VS    132
#define CO_AS2   68

__global__ void __launch_bounds__(256) chunk_out_mma_kernel(const float* __restrict__ g_w)
{
    extern __shared__ __align__(16) char smem[];
    const int tid = threadIdx.x, wid = tid >> 5, lane = tid & 31;
    const int n  = blockIdx.x;
    const int bh = blockIdx.y;
    const int b  = bh >> 3, h = bh & 7;
    const int row0 = b * TT + n * CH;
    const int col0 = h * DK;

    float* v_s    = (float*)(smem + CO_V);
    float* attn_s = (float*)(smem + CO_ATTN);
    float* Z_s    = (float*)(smem + CO_Z);
    float* den_s  = (float*)(smem + CO_DEN);
    float* red_s  = (float*)(smem + CO_RED);

    // ---- staging ----
    #pragma unroll
    for (int i = 0; i < 8; i++) {
        int lin = tid + i * 256;
        int r = lin >> 5, c4 = (lin & 31) * 4;
        size_t src = (size_t)(row0 + r) * DD + col0 + c4;
        uint2 hh, ll;
        split4(*(const float4*)&g_fq[src], hh, ll);
        *(uint2*)(smem + CO_FQ_HI + (r * CO_WS + c4) * 2) = hh;
        *(uint2*)(smem + CO_FQ_LO + (r * CO_WS + c4) * 2) = ll;
        split4(*(const float4*)&g_fk[src], hh, ll);
        *(uint2*)(smem + CO_FK_HI + (r * CO_WS + c4) * 2) = hh;
        *(uint2*)(smem + CO_FK_LO + (r * CO_WS + c4) * 2) = ll;
        *(float4*)&v_s[r * CO_VS + c4] = *(const float4*)&g_v[src];
    }
    size_t sbase = ((size_t)bh * NCH + n) * (DK * DV);
    #pragma unroll
    for (int i = 0; i < 16; i++) {
        int lin = tid + i * 256;
        int r = lin >> 5, c4 = (lin & 31) * 4;
        uint2 hh, ll;
        split4(*(const float4*)&g_S[sbase + (size_t)r * DV + c4], hh, ll);
        *(uint2*)(smem + CO_S_HI + (r * CO_WS + c4) * 2) = hh;
        *(uint2*)(smem + CO_S_LO + (r * CO_WS + c4) * 2) = ll;
    }
    if (tid < 32)
        *(float4*)&Z_s[tid * 4] = *(const float4*)&g_Z[((size_t)bh * NCH + n) * DK + tid * 4];
    __syncthreads();

    const int lr = lane >> 2, lk = (lane & 3) * 2;

    // ---- phase A: attn = fq @ fk^T  (M=64, N=64, K=128) ----
    {
        const int m0 = (wid & 3) * 16;
        const int n0 = (wid >> 2) * 32;
        float acc[4][4];
        #pragma unroll
        for (int ni = 0; ni < 4; ni++)
            #pragma unroll
            for (int t = 0; t < 4; t++) acc[ni][t] = 0.f;

        #pragma unroll
        for (int kk = 0; kk < 8; kk++) {
            int k0 = kk * 16;
            int mr = m0 + lr;
            uint32_t ah[4], al[4];
            ah[0] = *(uint32_t*)(smem + CO_FQ_HI + (mr * CO_WS + k0 + lk) * 2);
            ah[1] = *(uint32_t*)(smem + CO_FQ_HI + ((mr + 8) * CO_WS + k0 + lk) * 2);
            ah[2] = *(uint32_t*)(smem + CO_FQ_HI + (mr * CO_WS + k0 + 8 + lk) * 2);
            ah[3] = *(uint32_t*)(smem + CO_FQ_HI + ((mr + 8) * CO_WS + k0 + 8 + lk) * 2);
            al[0] = *(uint32_t*)(smem + CO_FQ_LO + (mr * CO_WS + k0 + lk) * 2);
            al[1] = *(uint32_t*)(smem + CO_FQ_LO + ((mr + 8) * CO_WS + k0 + lk) * 2);
            al[2] = *(uint32_t*)(smem + CO_FQ_LO + (mr * CO_WS + k0 + 8 + lk) * 2);
            al[3] = *(uint32_t*)(smem + CO_FQ_LO + ((mr + 8) * CO_WS + k0 + 8 + lk) * 2);
            #pragma unroll
            for (int ni = 0; ni < 4; ni++) {
                int nr = n0 + ni * 8 + lr;
                uint32_t bh[2], bl[2];
                bh[0] = *(uint32_t*)(smem + CO_FK_HI + (nr * CO_WS + k0 + lk) * 2);
                bh[1] = *(uint32_t*)(smem + CO_FK_HI + (nr * CO_WS + k0 + 8 + lk) * 2);
                bl[0] = *(uint32_t*)(smem + CO_FK_LO + (nr * CO_WS + k0 + lk) * 2);
                bl[1] = *(uint32_t*)(smem + CO_FK_LO + (nr * CO_WS + k0 + 8 + lk) * 2);
                MMA16816(acc[ni], ah, bh);
                MMA16816(acc[ni], ah, bl);
                MMA16816(acc[ni], al, bh);
            }
        }
        int r0 = m0 + lr, r1 = r0 + 8;
        #pragma unroll
        for (int ni = 0; ni < 4; ni++) {
            int c = n0 + ni * 8 + lk;
            attn_s[r0 * CO_AS2 + c]     = (c     <= r0) ? acc[ni][0] : 0.f;
            attn_s[r0 * CO_AS2 + c + 1] = (c + 1 <= r0) ? acc[ni][1] : 0.f;
            attn_s[r1 * CO_AS2 + c]     = (c     <= r1) ? acc[ni][2] : 0.f;
            attn_s[r1 * CO_AS2 + c + 1] = (c + 1 <= r1) ? acc[ni][3] : 0.f;
        }
    }
    __syncthreads();   // fk reads done; attn published

    // ---- phase B: o_inter = fq @ S_T  (M=64, N=128, K=128) ----
    float* o_s = (float*)(smem + CO_FK_HI);   // overlays fk (dead)
    {
        const int m0 = (wid & 3) * 16;
        const int n0 = (wid >> 2) * 64;
        float acc[8][4];
        #pragma unroll
        for (int ni = 0; ni < 8; ni++)
            #pragma unroll
            for (int t = 0; t < 4; t++) acc[ni][t] = 0.f;

        #pragma unroll
        for (int kk = 0; kk < 8; kk++) {
            int k0 = kk * 16;
            int mr = m0 + lr;
            uint32_t ah[4], al[4];
            ah[0] = *(uint32_t*)(smem + CO_FQ_HI + (mr * CO_WS + k0 + lk) * 2);
            ah[1] = *(uint32_t*)(smem + CO_FQ_HI + ((mr + 8) * CO_WS + k0 + lk) * 2);
            ah[2] = *(uint32_t*)(smem + CO_FQ_HI + (mr * CO_WS + k0 + 8 + lk) * 2);
            ah[3] = *(uint32_t*)(smem + CO_FQ_HI + ((mr + 8) * CO_WS + k0 + 8 + lk) * 2);
            al[0] = *(uint32_t*)(smem + CO_FQ_LO + (mr * CO_WS + k0 + lk) * 2);
            al[1] = *(uint32_t*)(smem + CO_FQ_LO + ((mr + 8) * CO_WS + k0 + lk) * 2);
            al[2] = *(uint32_t*)(smem + CO_FQ_LO + (mr * CO_WS + k0 + 8 + lk) * 2);
            al[3] = *(uint32_t*)(smem + CO_FQ_LO + ((mr + 8) * CO_WS + k0 + 8 + lk) * 2);
            #pragma unroll
            for (int ni = 0; ni < 8; ni++) {
                int nr = n0 + ni * 8 + lr;
                uint32_t bh[2], bl[2];
                bh[0] = *(uint32_t*)(smem + CO_S_HI + (nr * CO_WS + k0 + lk) * 2);
                bh[1] = *(uint32_t*)(smem + CO_S_HI + (nr * CO_WS + k0 + 8 + lk) * 2);
                bl[0] = *(uint32_t*)(smem + CO_S_LO + (nr * CO_WS + k0 + lk) * 2);
                bl[1] = *(uint32_t*)(smem + CO_S_LO + (nr * CO_WS + k0 + 8 + lk) * 2);
                MMA16816(acc[ni], ah, bh);
                MMA16816(acc[ni], ah, bl);
                MMA16816(acc[ni], al, bh);
            }
        }
        int r0 = m0 + lr;
        #pragma unroll
        for (int ni = 0; ni < 8; ni++) {
            int c = n0 + ni * 8 + lk;
            *(float2*)&o_s[r0 * CO_VS + c]       = make_float2(acc[ni][0], acc[ni][1]);
            *(float2*)&o_s[(r0 + 8) * CO_VS + c] = make_float2(acc[ni][2], acc[ni][3]);
        }
    }
    __syncthreads();

    // ---- phase C1: o += attn @ v  (FFMA, 4 rows x 8 cols per thread) ----
    {
        const int ty = tid >> 4;
        const int tx = tid & 15;
        const int e0 = tx * 8;
        float acc[4][8];
        #pragma unroll
        for (int i = 0; i < 4; i++) {
            float4 a0 = *(float4*)&o_s[(ty * 4 + i) * CO_VS + e0];
            float4 a1 = *(float4*)&o_s[(ty * 4 + i) * CO_VS + e0 + 4];
            acc[i][0] = a0.x; acc[i][1] = a0.y; acc[i][2] = a0.z; acc[i][3] = a0.w;
            acc[i][4] = a1.x; acc[i][5] = a1.y; acc[i][6] = a1.z; acc[i][7] = a1.w;
        }
        for (int m = 0; m < 64; m++) {
            float4 va = *(float4*)&v_s[m * CO_VS + e0];
            float4 vb = *(float4*)&v_s[m * CO_VS + e0 + 4];
            #pragma unroll
            for (int i = 0; i < 4; i++) {
                float a = attn_s[(ty * 4 + i) * CO_AS2 + m];
                acc[i][0] = fmaf(a, va.x, acc[i][0]);
                acc[i][1] = fmaf(a, va.y, acc[i][1]);
                acc[i][2] = fmaf(a, va.z, acc[i][2]);
                acc[i][3] = fmaf(a, va.w, acc[i][3]);
                acc[i][4] = fmaf(a, vb.x, acc[i][4]);
                acc[i][5] = fmaf(a, vb.y, acc[i][5]);
                acc[i][6] = fmaf(a, vb.z, acc[i][6]);
                acc[i][7] = fmaf(a, vb.w, acc[i][7]);
            }
        }
        #pragma unroll
        for (int i = 0; i < 4; i++) {
            *(float4*)&o_s[(ty * 4 + i) * CO_VS + e0]     = make_float4(acc[i][0], acc[i][1], acc[i][2], acc[i][3]);
            *(float4*)&o_s[(ty * 4 + i) * CO_VS + e0 + 4] = make_float4(acc[i][4], acc[i][5], acc[i][6], acc[i][7]);
        }
    }
    __syncthreads();

    // ---- phase C2: den + normalize + RMSNorm + float4 writeout ----
    {
        const int r  = tid >> 2;
        const int mq = tid & 3;
        float denp = 0.f;
        #pragma unroll 8
        for (int m = mq * 16; m < mq * 16 + 16; m++)
            denp += attn_s[r * CO_AS2 + m];
        #pragma unroll 8
        for (int d = mq * 32; d < mq * 32 + 32; d++) {
            float qv = __bfloat162float(*(__nv_bfloat16*)(smem + CO_FQ_HI + (r * CO_WS + d) * 2))
                     + __bfloat162float(*(__nv_bfloat16*)(smem + CO_FQ_LO + (r * CO_WS + d) * 2));
            denp += qv * Z_s[d];
        }
        den_s[tid] = denp;
        __syncthreads();
        float den = den_s[r * 4 + 0] + den_s[r * 4 + 1] + den_s[r * 4 + 2] + den_s[r * 4 + 3];
        float dinv = 1.f / (den + 1e-6f);
        float pp = 0.f;
        #pragma unroll
        for (int e = mq * 32; e < mq * 32 + 32; e += 4) {
            float4 val = *(float4*)&o_s[r * CO_VS + e];
            pp += (val.x * val.x + val.y * val.y + val.z * val.z + val.w * val.w);
        }
        pp *= dinv * dinv;
        red_s[tid] = pp;
        __syncthreads();
        float ms  = (red_s[r * 4 + 0] + red_s[r * 4 + 1] + red_s[r * 4 + 2] + red_s[r * 4 + 3]) * (1.f / 128.f);
        float rms = rsqrtf(ms + 1e-5f);
        float sc = dinv * rms;
        size_t obase = (size_t)(row0 + r) * DD + col0;
        #pragma unroll
        for (int e = mq * 32; e < mq * 32 + 32; e += 4) {
            float4 val = *(float4*)&o_s[r * CO_VS + e];
            float4 w4  = *(const float4*)&g_w[e];
            float4 o4 = make_float4(val.x * sc * w4.x, val.y * sc * w4.y,
                                    val.z * sc * w4.z, val.w * sc * w4.w);
            *(float4*)&g_o[obase + e] = o4;
        }
    }
}

// ============================================================================
// launch
// ============================================================================
extern "C" void kernel_launch(void* const* d_in, const int* in_sizes, int n_in,
                              void* d_out, int out_size)
{
    const float* x    = (const float*)d_in[0];
    const float* Wq   = (const float*)d_in[1];
    const float* Wk   = (const float*)d_in[2];
    const float* Wv   = (const float*)d_in[3];
    const float* Wo   = (const float*)d_in[4];
    const float* fq1w = (const float*)d_in[5];
    const float* fq1b = (const float*)d_in[6];
    const float* fq2w = (const float*)d_in[7];
    const float* fq2b = (const float*)d_in[8];
    const float* fk1w = (const float*)d_in[9];
    const float* fk1b = (const float*)d_in[10];
    const float* fk2w = (const float*)d_in[11];
    const float* fk2b = (const float*)d_in[12];
    const float* gw   = (const float*)d_in[13];
    float* out = (float*)d_out;

    cudaFuncSetAttribute(qkv_gemm_kernel,      cudaFuncAttributeMaxDynamicSharedMemorySize, MG_SMEM);
    cudaFuncSetAttribute(mma_gemm_kernel,      cudaFuncAttributeMaxDynamicSharedMemorySize, MG_SMEM);
    cudaFuncSetAttribute(featmap_mma_kernel,   cudaFuncAttributeMaxDynamicSharedMemorySize, FM_SMEM);
    cudaFuncSetAttribute(chunk_kv_mma_kernel,  cudaFuncAttributeMaxDynamicSharedMemorySize, KV_SMEM);
    cudaFuncSetAttribute(chunk_out_mma_kernel, cudaFuncAttributeMaxDynamicSharedMemorySize, CO_SMEM);

    float *q_p, *k_p, *v_p, *fq_p, *fk_p, *o_p;
    __nv_bfloat16 *ahi_p, *alo_p, *wthi_p, *wtlo_p, *fwhi_p, *fwlo_p;
    cudaGetSymbolAddress((void**)&q_p,  g_q);
    cudaGetSymbolAddress((void**)&k_p,  g_k);
    cudaGetSymbolAddress((void**)&v_p,  g_v);
    cudaGetSymbolAddress((void**)&fq_p, g_fq);
    cudaGetSymbolAddress((void**)&fk_p, g_fk);
    cudaGetSymbolAddress((void**)&o_p,  g_o);
    cudaGetSymbolAddress((void**)&ahi_p, g_ahi);
    cudaGetSymbolAddress((void**)&alo_p, g_alo);
    cudaGetSymbolAddress((void**)&wthi_p, g_wthi);
    cudaGetSymbolAddress((void**)&wtlo_p, g_wtlo);
    cudaGetSymbolAddress((void**)&fwhi_p, g_fwhi);
    cudaGetSymbolAddress((void**)&fwlo_p, g_fwlo);

    const size_t WSZ = (size_t)DD * DD;
    const int FWSZ = DK * DK;
    dim3 tblk(32, 8), tgrd(32, 32), tgrd128(4, 4);
    transpose_split_kernel<<<tgrd, tblk>>>(Wq, wthi_p + 0 * WSZ, wtlo_p + 0 * WSZ);
    transpose_split_kernel<<<tgrd, tblk>>>(Wk, wthi_p + 1 * WSZ, wtlo_p + 1 * WSZ);
    transpose_split_kernel<<<tgrd, tblk>>>(Wv, wthi_p + 2 * WSZ, wtlo_p + 2 * WSZ);
    transpose_split_kernel<<<tgrd, tblk>>>(Wo, wthi_p + 3 * WSZ, wtlo_p + 3 * WSZ);
    transpose_split128_kernel<<<tgrd128, tblk>>>(fq1w, fwhi_p + 0 * FWSZ, fwlo_p + 0 * FWSZ);
    transpose_split128_kernel<<<tgrd128, tblk>>>(fq2w, fwhi_p + 1 * FWSZ, fwlo_p + 1 * FWSZ);
    transpose_split128_kernel<<<tgrd128, tblk>>>(fk1w, fwhi_p + 2 * FWSZ, fwlo_p + 2 * FWSZ);
    transpose_split128_kernel<<<tgrd128, tblk>>>(fk2w, fwhi_p + 3 * FWSZ, fwlo_p + 3 * FWSZ);

    split_kernel<<<8192, 256>>>(x, ahi_p, alo_p);

    qkv_gemm_kernel<<<dim3(24, TTOT / 128), 256, MG_SMEM>>>(
        ahi_p, alo_p, wthi_p, wtlo_p, q_p, k_p, v_p);

    featmap_mma_kernel<<<dim3(TTOT / 128, HH, 2), 256, FM_SMEM>>>(
        q_p, k_p, fwhi_p, fwlo_p, fq1b, fq2b, fk1b, fk2b, fq_p, fk_p);

    chunk_kv_mma_kernel<<<dim3(NCH, BHN), 256, KV_SMEM>>>();
    scan_kernel<<<dim3(16, BHN), 256>>>();
    chunk_out_mma_kernel<<<dim3(NCH, BHN), 256, CO_SMEM>>>(gw);

    split_kernel<<<8192, 256>>>(o_p, ahi_p, alo_p);
    mma_gemm_kernel<<<dim3(DD / 128, TTOT / 128), 256, MG_SMEM>>>(
        ahi_p, alo_p, wthi_p + 3 * WSZ, wtlo_p + 3 * WSZ, out);
}